// round 2
// baseline (speedup 1.0000x reference)
#include <cuda_runtime.h>

#define B_ROWS      8192
#define FEATURE_NUM 200
#define NUMERIC_SZ  100
#define IN_W        (FEATURE_NUM + NUMERIC_SZ)   // 300
#define EMBED       64
#define TPR         16                            // threads per row (4 dims each)
#define ROWS_PB     16                            // 256 threads / block
#define NTHREADS    (TPR * ROWS_PB)

__global__ __launch_bounds__(NTHREADS)
void fm_kernel(const float* __restrict__ inputs,
               const float* __restrict__ w_one_hot,
               const float* __restrict__ w_numeric,
               const float* __restrict__ v_one_hot,
               const float* __restrict__ v_numeric,
               const float* __restrict__ bias,
               float* __restrict__ out)
{
    __shared__ int   s_idx[ROWS_PB][FEATURE_NUM];
    __shared__ float s_num[ROWS_PB][NUMERIC_SZ];

    const int tid = threadIdx.x;
    const int e   = tid & (TPR - 1);      // 0..15 : which float4 of the row
    const int r   = tid >> 4;             // 0..15 : row within block
    const int row0 = blockIdx.x * ROWS_PB;

    // ---- stage indices + numerics for all 16 rows, fully coalesced ----
    {
        const float* base = inputs + (long)row0 * IN_W;
        for (int t = tid; t < ROWS_PB * IN_W; t += NTHREADS) {
            int rr = t / IN_W;
            int cc = t - rr * IN_W;
            float v = base[rr * IN_W + cc];
            if (cc < FEATURE_NUM) s_idx[rr][cc] = (int)v;
            else                  s_num[rr][cc - FEATURE_NUM] = v;
        }
    }
    __syncthreads();

    const float4* __restrict__ vtab = (const float4*)v_one_hot;   // id*16 + e
    const float4* __restrict__ vnum = (const float4*)v_numeric;   // k*16 + e

    // ---- sparse gather: per-dim sum + sum of squares (4 dims / thread) ----
    float4 s  = make_float4(0.f, 0.f, 0.f, 0.f);
    float4 ss = make_float4(0.f, 0.f, 0.f, 0.f);

    #pragma unroll 8
    for (int j = 0; j < FEATURE_NUM; j++) {
        int id = s_idx[r][j];
        float4 v = __ldg(&vtab[(long)id * TPR + e]);   // 16B of the 256B row
        s.x += v.x;  s.y += v.y;  s.z += v.z;  s.w += v.w;
        ss.x = fmaf(v.x, v.x, ss.x);
        ss.y = fmaf(v.y, v.y, ss.y);
        ss.z = fmaf(v.z, v.z, ss.z);
        ss.w = fmaf(v.w, v.w, ss.w);
    }

    // ---- first-order sparse part (4MB table, mostly L2-resident) ----
    float fo = 0.f;
    #pragma unroll
    for (int j = e; j < FEATURE_NUM; j += TPR)
        fo += __ldg(&w_one_hot[s_idx[r][j]]);

    // ---- dense numeric part ----
    #pragma unroll 4
    for (int k = 0; k < NUMERIC_SZ; k++) {
        float  n  = s_num[r][k];
        float4 vn = __ldg(&vnum[k * TPR + e]);         // 25.6KB, cache-resident
        float tx = n * vn.x, ty = n * vn.y, tz = n * vn.z, tw = n * vn.w;
        s.x += tx;  s.y += ty;  s.z += tz;  s.w += tw;
        ss.x = fmaf(tx, tx, ss.x);
        ss.y = fmaf(ty, ty, ss.y);
        ss.z = fmaf(tz, tz, ss.z);
        ss.w = fmaf(tw, tw, ss.w);
    }
    #pragma unroll
    for (int k = e; k < NUMERIC_SZ; k += TPR)
        fo = fmaf(s_num[r][k], __ldg(&w_numeric[k]), fo);

    // ---- per-thread second-order contribution over its 4 dims ----
    float so = fmaf(s.x, s.x, -ss.x) + fmaf(s.y, s.y, -ss.y)
             + fmaf(s.z, s.z, -ss.z) + fmaf(s.w, s.w, -ss.w);
    float val = fmaf(0.5f, so, fo);

    // ---- reduce across the 16 threads of this row (width-16 shuffles) ----
    #pragma unroll
    for (int off = 8; off > 0; off >>= 1)
        val += __shfl_xor_sync(0xffffffffu, val, off, TPR);

    if (e == 0)
        out[row0 + r] = val + bias[0];
}

extern "C" void kernel_launch(void* const* d_in, const int* in_sizes, int n_in,
                              void* d_out, int out_size)
{
    const float* inputs    = (const float*)d_in[0];
    const float* w_one_hot = (const float*)d_in[1];
    const float* w_numeric = (const float*)d_in[2];
    const float* v_one_hot = (const float*)d_in[3];
    const float* v_numeric = (const float*)d_in[4];
    const float* bias      = (const float*)d_in[5];
    float* out = (float*)d_out;

    fm_kernel<<<B_ROWS / ROWS_PB, NTHREADS>>>(inputs, w_one_hot, w_numeric,
                                              v_one_hot, v_numeric, bias, out);
}

// round 3
// speedup vs baseline: 1.0733x; 1.0733x over previous
#include <cuda_runtime.h>

#define B_ROWS      8192
#define FEATURE_NUM 200
#define NUMERIC_SZ  100
#define IN_W        (FEATURE_NUM + NUMERIC_SZ)   // 300
#define EMBED       64
#define ROWS_PB     4
#define HOT_IDS     420000   // ~107MB of the 256MB table kept L2-resident

__device__ __forceinline__ float ldg_pol(const float* p, unsigned long long pol)
{
    float v;
    asm volatile("ld.global.nc.L2::cache_hint.f32 %0, [%1], %2;"
                 : "=f"(v) : "l"(p), "l"(pol));
    return v;
}

__global__ __launch_bounds__(EMBED * ROWS_PB)
void fm_kernel(const float* __restrict__ inputs,
               const float* __restrict__ w_one_hot,
               const float* __restrict__ w_numeric,
               const float* __restrict__ v_one_hot,
               const float* __restrict__ v_numeric,
               const float* __restrict__ bias,
               float* __restrict__ out)
{
    __shared__ int   s_idx[ROWS_PB][FEATURE_NUM];
    __shared__ float s_num[ROWS_PB][NUMERIC_SZ];
    __shared__ float s_wpart[ROWS_PB][2];

    unsigned long long pol_last, pol_first;
    asm("createpolicy.fractional.L2::evict_last.b64 %0, 1.0;"  : "=l"(pol_last));
    asm("createpolicy.fractional.L2::evict_first.b64 %0, 1.0;" : "=l"(pol_first));

    const int e   = threadIdx.x;          // 0..63 : embed dim
    const int r   = threadIdx.y;          // 0..3  : row within block
    const int row = blockIdx.x * ROWS_PB + r;

    const float* in_row = inputs + (long)row * IN_W;

    // Stage indices (cast float->int) and numeric features into shared.
    #pragma unroll
    for (int j = e; j < FEATURE_NUM; j += EMBED)
        s_idx[r][j] = (int)in_row[j];
    #pragma unroll
    for (int k = e; k < NUMERIC_SZ; k += EMBED)
        s_num[r][k] = in_row[FEATURE_NUM + k];
    __syncthreads();

    // ---- sparse gather: sum and sum-of-squares over 200 embedding rows ----
    // Hot ids (< HOT_IDS) pinned with evict_last; cold ids stream evict_first
    // so they never displace the hot working set.
    float s = 0.f, ss = 0.f;
    #pragma unroll 8
    for (int j = 0; j < FEATURE_NUM; j++) {
        int id = s_idx[r][j];
        unsigned long long pol = (id < HOT_IDS) ? pol_last : pol_first;
        float v = ldg_pol(&v_one_hot[id * EMBED + e], pol);
        s  += v;
        ss  = fmaf(v, v, ss);
    }

    // ---- first-order sparse part (4MB table: pin it) ----
    float fo = 0.f;
    #pragma unroll
    for (int j = e; j < FEATURE_NUM; j += EMBED)
        fo += ldg_pol(&w_one_hot[s_idx[r][j]], pol_last);

    // ---- dense numeric part ----
    #pragma unroll 4
    for (int k = 0; k < NUMERIC_SZ; k++) {
        float n  = s_num[r][k];
        float vn = __ldg(&v_numeric[k * EMBED + e]);   // 25.6KB, cache-resident
        float t  = n * vn;
        s  += t;
        ss  = fmaf(t, t, ss);
    }
    #pragma unroll
    for (int k = e; k < NUMERIC_SZ; k += EMBED)
        fo = fmaf(s_num[r][k], __ldg(&w_numeric[k]), fo);

    // ---- combine + reduce over the 64 threads of this row (2 warps) ----
    float val = fmaf(0.5f, fmaf(s, s, -ss), fo);

    #pragma unroll
    for (int off = 16; off > 0; off >>= 1)
        val += __shfl_down_sync(0xffffffffu, val, off);

    const int lane = e & 31;
    const int warp = e >> 5;
    if (lane == 0) s_wpart[r][warp] = val;
    __syncthreads();

    if (e == 0)
        out[row] = s_wpart[r][0] + s_wpart[r][1] + bias[0];
}

extern "C" void kernel_launch(void* const* d_in, const int* in_sizes, int n_in,
                              void* d_out, int out_size)
{
    const float* inputs    = (const float*)d_in[0];
    const float* w_one_hot = (const float*)d_in[1];
    const float* w_numeric = (const float*)d_in[2];
    const float* v_one_hot = (const float*)d_in[3];
    const float* v_numeric = (const float*)d_in[4];
    const float* bias      = (const float*)d_in[5];
    float* out = (float*)d_out;

    dim3 block(EMBED, ROWS_PB);
    dim3 grid(B_ROWS / ROWS_PB);
    fm_kernel<<<grid, block>>>(inputs, w_one_hot, w_numeric,
                               v_one_hot, v_numeric, bias, out);
}

// round 4
// speedup vs baseline: 1.0991x; 1.0241x over previous
#include <cuda_runtime.h>

#define B_ROWS      8192
#define FEATURE_NUM 200
#define NUMERIC_SZ  100
#define IN_W        (FEATURE_NUM + NUMERIC_SZ)   // 300
#define EMBED       64
#define ROWS_PB     8                             // one warp per row
#define NTHREADS    (32 * ROWS_PB)                // 256
#define NBINS       64                            // id >> 14 -> 0..61
#define HOT_IDS     380000                        // ~97MB pinned in L2

__device__ __forceinline__ float2 ldg2_pol(const float* p, unsigned long long pol)
{
    float2 v;
    asm volatile("ld.global.nc.L2::cache_hint.v2.f32 {%0,%1}, [%2], %3;"
                 : "=f"(v.x), "=f"(v.y) : "l"(p), "l"(pol));
    return v;
}
__device__ __forceinline__ float ldg_pol(const float* p, unsigned long long pol)
{
    float v;
    asm volatile("ld.global.nc.L2::cache_hint.f32 %0, [%1], %2;"
                 : "=f"(v) : "l"(p), "l"(pol));
    return v;
}

__global__ __launch_bounds__(NTHREADS)
void fm_kernel(const float* __restrict__ inputs,
               const float* __restrict__ w_one_hot,
               const float* __restrict__ w_numeric,
               const float* __restrict__ v_one_hot,
               const float* __restrict__ v_numeric,
               const float* __restrict__ bias,
               float* __restrict__ out)
{
    __shared__ int   s_raw[ROWS_PB][FEATURE_NUM];
    __shared__ int   s_sorted[ROWS_PB][FEATURE_NUM];
    __shared__ float s_num[ROWS_PB][NUMERIC_SZ];
    __shared__ int   s_bin[ROWS_PB][NBINS];

    unsigned long long pol_last, pol_first;
    asm("createpolicy.fractional.L2::evict_last.b64 %0, 1.0;"  : "=l"(pol_last));
    asm("createpolicy.fractional.L2::evict_first.b64 %0, 1.0;" : "=l"(pol_first));

    const int tid  = threadIdx.x;
    const int lane = tid & 31;
    const int r    = tid >> 5;                    // row within block (warp id)
    const int row0 = blockIdx.x * ROWS_PB;

    // ---- stage inputs (coalesced across the whole block) ----
    {
        const float* base = inputs + (long)row0 * IN_W;
        for (int t = tid; t < ROWS_PB * IN_W; t += NTHREADS) {
            int rr = t / IN_W, cc = t - rr * IN_W;
            float v = base[rr * IN_W + cc];
            if (cc < FEATURE_NUM) s_raw[rr][cc] = (int)v;
            else                  s_num[rr][cc - FEATURE_NUM] = v;
        }
        for (int t = tid; t < ROWS_PB * NBINS; t += NTHREADS)
            ((int*)s_bin)[t] = 0;
    }
    __syncthreads();

    // ---- approximate sort of this row's ids (64-way bucket by id>>14) ----
    // Monotone sweep order => all resident rows stream the table in near
    // lockstep => cold lines get their ~1.64x reuse from transient L2.
    #pragma unroll
    for (int j = lane; j < FEATURE_NUM; j += 32)
        atomicAdd(&s_bin[r][s_raw[r][j] >> 14], 1);
    __syncwarp();
    if (lane == 0) {                               // exclusive prefix, serial (64)
        int acc = 0;
        #pragma unroll
        for (int b = 0; b < NBINS; b++) { int c = s_bin[r][b]; s_bin[r][b] = acc; acc += c; }
    }
    __syncwarp();
    #pragma unroll
    for (int j = lane; j < FEATURE_NUM; j += 32) {
        int id  = s_raw[r][j];
        int pos = atomicAdd(&s_bin[r][id >> 14], 1);
        s_sorted[r][pos] = id;
    }
    __syncwarp();

    // ---- sparse gather in ascending-id order: sum + sum of squares ----
    // Each lane owns 2 embed dims (float2). Hot prefix pinned evict_last.
    float2 s  = make_float2(0.f, 0.f);
    float2 ss = make_float2(0.f, 0.f);
    const int c0 = lane * 2;

    #pragma unroll 8
    for (int j = 0; j < FEATURE_NUM; j++) {
        int id = s_sorted[r][j];
        unsigned long long pol = (id < HOT_IDS) ? pol_last : pol_first;
        float2 v = ldg2_pol(&v_one_hot[(long)id * EMBED + c0], pol);
        s.x += v.x;  s.y += v.y;
        ss.x = fmaf(v.x, v.x, ss.x);
        ss.y = fmaf(v.y, v.y, ss.y);
    }

    // ---- first-order sparse part (4MB table: pinned) ----
    float fo = 0.f;
    #pragma unroll
    for (int j = lane; j < FEATURE_NUM; j += 32)
        fo += ldg_pol(&w_one_hot[s_sorted[r][j]], pol_last);

    // ---- dense numeric part ----
    #pragma unroll 4
    for (int k = 0; k < NUMERIC_SZ; k++) {
        float  n  = s_num[r][k];
        float2 vn = *(const float2*)&v_numeric[k * EMBED + c0];  // cache-resident
        float tx = n * vn.x, ty = n * vn.y;
        s.x += tx;  s.y += ty;
        ss.x = fmaf(tx, tx, ss.x);
        ss.y = fmaf(ty, ty, ss.y);
    }
    #pragma unroll
    for (int k = lane; k < NUMERIC_SZ; k += 32)
        fo = fmaf(s_num[r][k], __ldg(&w_numeric[k]), fo);

    // ---- combine + warp reduce (one warp == one row) ----
    float so  = fmaf(s.x, s.x, -ss.x) + fmaf(s.y, s.y, -ss.y);
    float val = fmaf(0.5f, so, fo);

    #pragma unroll
    for (int off = 16; off > 0; off >>= 1)
        val += __shfl_xor_sync(0xffffffffu, val, off);

    if (lane == 0)
        out[row0 + r] = val + bias[0];
}

extern "C" void kernel_launch(void* const* d_in, const int* in_sizes, int n_in,
                              void* d_out, int out_size)
{
    const float* inputs    = (const float*)d_in[0];
    const float* w_one_hot = (const float*)d_in[1];
    const float* w_numeric = (const float*)d_in[2];
    const float* v_one_hot = (const float*)d_in[3];
    const float* v_numeric = (const float*)d_in[4];
    const float* bias      = (const float*)d_in[5];
    float* out = (float*)d_out;

    fm_kernel<<<B_ROWS / ROWS_PB, NTHREADS>>>(inputs, w_one_hot, w_numeric,
                                              v_one_hot, v_numeric, bias, out);
}

// round 6
// speedup vs baseline: 1.1358x; 1.0334x over previous
#include <cuda_runtime.h>
#include <cstdint>

#define B_ROWS      8192
#define FEATURE_NUM 200
#define NUMERIC_SZ  100
#define IN_W        (FEATURE_NUM + NUMERIC_SZ)   // 300
#define EMBED       64
#define ROWS_PB     8                             // one warp per row
#define NTHREADS    (32 * ROWS_PB)                // 256
#define NBINS       64                            // id >> 14
#define HOT_IDS     380000                        // ~97MB pinned in L2
#define CH          4                             // ids per pipeline stage
#define NSTAGES     (FEATURE_NUM / CH)            // 50
#define STAGE_B     (CH * EMBED * 4)              // 1024 bytes

__device__ __forceinline__ float ldg_pol(const float* p, unsigned long long pol)
{
    float v;
    asm volatile("ld.global.nc.L2::cache_hint.f32 %0, [%1], %2;"
                 : "=f"(v) : "l"(p), "l"(pol));
    return v;
}

__global__ __launch_bounds__(NTHREADS)
void fm_kernel(const float* __restrict__ inputs,
               const float* __restrict__ w_one_hot,
               const float* __restrict__ w_numeric,
               const float* __restrict__ v_one_hot,
               const float* __restrict__ v_numeric,
               const float* __restrict__ bias,
               float* __restrict__ out)
{
    __shared__ int   s_sorted[ROWS_PB][FEATURE_NUM];
    __shared__ float s_num[ROWS_PB][NUMERIC_SZ];
    __shared__ int   s_bin[ROWS_PB][NBINS];
    __shared__ __align__(16) char s_buf[ROWS_PB][2][STAGE_B];

    unsigned long long pol_last, pol_first;
    asm("createpolicy.fractional.L2::evict_last.b64 %0, 1.0;"  : "=l"(pol_last));
    asm("createpolicy.fractional.L2::evict_first.b64 %0, 1.0;" : "=l"(pol_first));

    const int tid  = threadIdx.x;
    const int lane = tid & 31;
    const int r    = tid >> 5;
    const int row  = blockIdx.x * ROWS_PB + r;
    const float* in_row = inputs + (long)row * IN_W;

    // ---- per-warp: zero bins, load ids to regs, histogram ----
    s_bin[r][lane] = 0;  s_bin[r][lane + 32] = 0;
    __syncwarp();

    int my_id[7];
    #pragma unroll
    for (int k = 0; k < 7; k++) {
        int j = lane + k * 32;
        my_id[k] = (j < FEATURE_NUM) ? (int)in_row[j] : -1;
        if (my_id[k] >= 0) atomicAdd(&s_bin[r][my_id[k] >> 14], 1);
    }
    // numeric features (warp-local staging)
    #pragma unroll
    for (int k = lane; k < NUMERIC_SZ; k += 32)
        s_num[r][k] = in_row[FEATURE_NUM + k];
    __syncwarp();

    // ---- warp-parallel exclusive prefix over 64 bins ----
    {
        int c0 = s_bin[r][lane], c1 = s_bin[r][lane + 32];
        int i0 = c0, i1 = c1;
        #pragma unroll
        for (int off = 1; off < 32; off <<= 1) {
            int t0 = __shfl_up_sync(0xffffffffu, i0, off);
            int t1 = __shfl_up_sync(0xffffffffu, i1, off);
            if (lane >= off) { i0 += t0; i1 += t1; }
        }
        int tot0 = __shfl_sync(0xffffffffu, i0, 31);
        i1 += tot0;
        s_bin[r][lane]      = i0 - c0;
        s_bin[r][lane + 32] = i1 - c1;
    }
    __syncwarp();

    // ---- scatter into ascending-bin order (approximate sort) ----
    #pragma unroll
    for (int k = 0; k < 7; k++)
        if (my_id[k] >= 0) {
            int pos = atomicAdd(&s_bin[r][my_id[k] >> 14], 1);
            s_sorted[r][pos] = my_id[k];
        }
    __syncwarp();

    // ---- cp.async pipelined gather: register-free MLP ----
    const unsigned int buf0 =
        (unsigned int)__cvta_generic_to_shared(&s_buf[r][0][0]);

    auto issue_stage = [&](int st, int slot) {
        unsigned int dst = buf0 + slot * STAGE_B;
        #pragma unroll
        for (int t = 0; t < 2; t++) {
            int c  = lane + t * 32;                  // 0..63 : 16B chunk
            int id = s_sorted[r][st * CH + (c >> 4)];
            const char* src = (const char*)(v_one_hot + (long)id * EMBED)
                            + (c & 15) * 16;
            unsigned long long pol = (id < HOT_IDS) ? pol_last : pol_first;
            asm volatile("cp.async.cg.shared.global.L2::cache_hint [%0], [%1], 16, %2;"
                         :: "r"(dst + c * 16), "l"(src), "l"(pol) : "memory");
        }
        asm volatile("cp.async.commit_group;" ::: "memory");
    };

    float2 s  = make_float2(0.f, 0.f);
    float2 ss = make_float2(0.f, 0.f);

    issue_stage(0, 0);
    issue_stage(1, 1);

    #pragma unroll 1
    for (int st = 0; st < NSTAGES; st++) {
        if (st + 2 < NSTAGES)
            asm volatile("cp.async.wait_group 1;" ::: "memory");
        else
            asm volatile("cp.async.wait_group 0;" ::: "memory");
        __syncwarp();

        const float2* bp = (const float2*)&s_buf[r][st & 1][0];
        #pragma unroll
        for (int i = 0; i < CH; i++) {
            float2 v = bp[i * 32 + lane];            // columns 2*lane, 2*lane+1
            s.x += v.x;  s.y += v.y;
            ss.x = fmaf(v.x, v.x, ss.x);
            ss.y = fmaf(v.y, v.y, ss.y);
        }
        __syncwarp();
        if (st + 2 < NSTAGES) issue_stage(st + 2, st & 1);
    }

    // ---- first-order sparse part (4MB table: pinned, L2 hits) ----
    float fo = 0.f;
    #pragma unroll
    for (int k = 0; k < 7; k++) {
        int j = lane + k * 32;
        if (j < FEATURE_NUM)
            fo += ldg_pol(&w_one_hot[s_sorted[r][j]], pol_last);
    }

    // ---- dense numeric part ----
    const int c0 = lane * 2;
    #pragma unroll 4
    for (int k = 0; k < NUMERIC_SZ; k++) {
        float  n  = s_num[r][k];
        float2 vn = *(const float2*)&v_numeric[k * EMBED + c0];
        float tx = n * vn.x, ty = n * vn.y;
        s.x += tx;  s.y += ty;
        ss.x = fmaf(tx, tx, ss.x);
        ss.y = fmaf(ty, ty, ss.y);
    }
    #pragma unroll
    for (int k = lane; k < NUMERIC_SZ; k += 32)
        fo = fmaf(s_num[r][k], __ldg(&w_numeric[k]), fo);

    // ---- combine + warp reduce ----
    float so  = fmaf(s.x, s.x, -ss.x) + fmaf(s.y, s.y, -ss.y);
    float val = fmaf(0.5f, so, fo);

    #pragma unroll
    for (int off = 16; off > 0; off >>= 1)
        val += __shfl_xor_sync(0xffffffffu, val, off);

    if (lane == 0)
        out[row] = val + bias[0];
}

extern "C" void kernel_launch(void* const* d_in, const int* in_sizes, int n_in,
                              void* d_out, int out_size)
{
    const float* inputs    = (const float*)d_in[0];
    const float* w_one_hot = (const float*)d_in[1];
    const float* w_numeric = (const float*)d_in[2];
    const float* v_one_hot = (const float*)d_in[3];
    const float* v_numeric = (const float*)d_in[4];
    const float* bias      = (const float*)d_in[5];
    float* out = (float*)d_out;

    fm_kernel<<<B_ROWS / ROWS_PB, NTHREADS>>>(inputs, w_one_hot, w_numeric,
                                              v_one_hot, v_numeric, bias, out);
}